// round 1
// baseline (speedup 1.0000x reference)
#include <cuda_runtime.h>

// Problem constants
#define BATCH  4
#define SEQ    2048
#define DMODEL 512
#define NHEAD  8
#define DEPTH  64
#define ROWS   (BATCH * SEQ)          // 8192
#define BH     (BATCH * NHEAD)        // 32
#define SCALE  0.125f                 // 1/sqrt(DEPTH)

// Scratch (device globals — no allocation allowed in kernel_launch)
__device__ float g_q[BH * SEQ * DEPTH];     // [b,h,s,d]
__device__ float g_k[BH * SEQ * DEPTH];
__device__ float g_v[BH * SEQ * DEPTH];
__device__ float g_ctx[ROWS * DMODEL];      // [b,s,D]

// ---------------------------------------------------------------------------
// K1: fused QKV projection. Y = x @ W + b, written in head-split layout.
// grid: (DMODEL/64, ROWS/64, 3); block: 256 threads; 64x64 tile, 4x4 micro.
// ---------------------------------------------------------------------------
__global__ __launch_bounds__(256) void qkv_gemm(
    const float* __restrict__ x,
    const float* __restrict__ Wq, const float* __restrict__ bq,
    const float* __restrict__ Wk, const float* __restrict__ bk,
    const float* __restrict__ Wv, const float* __restrict__ bv)
{
    const float* W; const float* bias; float* out;
    if (blockIdx.z == 0)      { W = Wq; bias = bq; out = g_q; }
    else if (blockIdx.z == 1) { W = Wk; bias = bk; out = g_k; }
    else                      { W = Wv; bias = bv; out = g_v; }

    __shared__ float As[64][17];   // [m][k] padded
    __shared__ float Bs[16][65];   // [k][n] padded

    const int row0 = blockIdx.y * 64;
    const int col0 = blockIdx.x * 64;
    const int tid  = threadIdx.x;
    const int tx   = tid & 15;
    const int ty   = tid >> 4;

    float acc[4][4] = {};

    for (int k0 = 0; k0 < DMODEL; k0 += 16) {
        // load A tile 64x16
        {
            const int c = tid & 15;
            const int r = tid >> 4;            // 16 rows per pass
            #pragma unroll
            for (int p = 0; p < 4; p++)
                As[r + p * 16][c] = x[(size_t)(row0 + r + p * 16) * DMODEL + k0 + c];
        }
        // load B tile 16x64
        {
            const int c = tid & 63;
            const int r = tid >> 6;            // 4 rows per pass
            #pragma unroll
            for (int p = 0; p < 4; p++)
                Bs[r + p * 4][c] = W[(size_t)(k0 + r + p * 4) * DMODEL + col0 + c];
        }
        __syncthreads();

        #pragma unroll
        for (int kk = 0; kk < 16; kk++) {
            float a[4], bb[4];
            #pragma unroll
            for (int i = 0; i < 4; i++) a[i]  = As[ty * 4 + i][kk];
            #pragma unroll
            for (int j = 0; j < 4; j++) bb[j] = Bs[kk][tx * 4 + j];
            #pragma unroll
            for (int i = 0; i < 4; i++)
                #pragma unroll
                for (int j = 0; j < 4; j++)
                    acc[i][j] = fmaf(a[i], bb[j], acc[i][j]);
        }
        __syncthreads();
    }

    #pragma unroll
    for (int i = 0; i < 4; i++) {
        const int row = row0 + ty * 4 + i;
        const int b   = row / SEQ;
        const int s   = row % SEQ;
        #pragma unroll
        for (int j = 0; j < 4; j++) {
            const int col = col0 + tx * 4 + j;
            const int h   = col / DEPTH;
            const int d   = col % DEPTH;
            out[(size_t)((b * NHEAD + h) * SEQ + s) * DEPTH + d] = acc[i][j] + bias[col];
        }
    }
}

// ---------------------------------------------------------------------------
// K2: logits = q @ k^T * SCALE  (per b,h).  grid: (SEQ/64, SEQ/64, BH)
// ---------------------------------------------------------------------------
__global__ __launch_bounds__(256) void logits_kernel(float* __restrict__ attn)
{
    const int bh = blockIdx.z;
    const float* q = g_q + (size_t)bh * SEQ * DEPTH;
    const float* k = g_k + (size_t)bh * SEQ * DEPTH;
    float* out = attn + (size_t)bh * SEQ * SEQ;

    __shared__ float Qs[64][65];
    __shared__ float Ks[64][65];

    const int qrow0 = blockIdx.y * 64;
    const int kcol0 = blockIdx.x * 64;
    const int tid   = threadIdx.x;
    const int tx    = tid & 15;
    const int ty    = tid >> 4;

    {
        const int c = tid & 63;
        const int r = tid >> 6;             // 4 rows per pass, 16 passes
        #pragma unroll
        for (int p = 0; p < 16; p++) {
            Qs[r + p * 4][c] = q[(size_t)(qrow0 + r + p * 4) * DEPTH + c];
            Ks[r + p * 4][c] = k[(size_t)(kcol0 + r + p * 4) * DEPTH + c];
        }
    }
    __syncthreads();

    float acc[4][4] = {};
    #pragma unroll
    for (int kk = 0; kk < DEPTH; kk++) {
        float a[4], bb[4];
        #pragma unroll
        for (int i = 0; i < 4; i++) a[i]  = Qs[ty * 4 + i][kk];
        #pragma unroll
        for (int j = 0; j < 4; j++) bb[j] = Ks[tx * 4 + j][kk];
        #pragma unroll
        for (int i = 0; i < 4; i++)
            #pragma unroll
            for (int j = 0; j < 4; j++)
                acc[i][j] = fmaf(a[i], bb[j], acc[i][j]);
    }

    #pragma unroll
    for (int i = 0; i < 4; i++) {
        const size_t rbase = (size_t)(qrow0 + ty * 4 + i) * SEQ + kcol0;
        #pragma unroll
        for (int j = 0; j < 4; j++)
            out[rbase + tx * 4 + j] = acc[i][j] * SCALE;
    }
}

// ---------------------------------------------------------------------------
// K3: in-place softmax over last dim. One block per row of length SEQ=2048.
// ---------------------------------------------------------------------------
__global__ __launch_bounds__(256) void softmax_kernel(float* __restrict__ attn)
{
    float* p = attn + (size_t)blockIdx.x * SEQ;
    const int tid = threadIdx.x;

    float v[8];
    float m = -1e30f;
    #pragma unroll
    for (int i = 0; i < 8; i++) {
        v[i] = p[tid + i * 256];
        m = fmaxf(m, v[i]);
    }

    __shared__ float red[256];
    red[tid] = m;
    __syncthreads();
    #pragma unroll
    for (int s = 128; s > 0; s >>= 1) {
        if (tid < s) red[tid] = fmaxf(red[tid], red[tid + s]);
        __syncthreads();
    }
    m = red[0];
    __syncthreads();

    float sum = 0.f;
    #pragma unroll
    for (int i = 0; i < 8; i++) {
        v[i] = __expf(v[i] - m);
        sum += v[i];
    }
    red[tid] = sum;
    __syncthreads();
    #pragma unroll
    for (int s = 128; s > 0; s >>= 1) {
        if (tid < s) red[tid] += red[tid + s];
        __syncthreads();
    }
    const float inv = 1.f / red[0];

    #pragma unroll
    for (int i = 0; i < 8; i++)
        p[tid + i * 256] = v[i] * inv;
}

// ---------------------------------------------------------------------------
// K4: ctx = attn @ v  (per b,h), written to [B,S,D] layout.
// grid: (1, SEQ/64, BH). Block computes 64 q-rows x full DEPTH=64.
// ---------------------------------------------------------------------------
__global__ __launch_bounds__(256) void ctx_kernel(const float* __restrict__ attn)
{
    const int bh = blockIdx.z;
    const int b  = bh / NHEAD;
    const int h  = bh % NHEAD;
    const float* A = attn + (size_t)bh * SEQ * SEQ;
    const float* V = g_v  + (size_t)bh * SEQ * DEPTH;

    __shared__ float As[64][65];
    __shared__ float Vs[64][65];

    const int row0 = blockIdx.y * 64;
    const int tid  = threadIdx.x;
    const int tx   = tid & 15;
    const int ty   = tid >> 4;

    float acc[4][4] = {};

    for (int k0 = 0; k0 < SEQ; k0 += 64) {
        const int c = tid & 63;
        const int r = tid >> 6;
        #pragma unroll
        for (int p = 0; p < 16; p++) {
            As[r + p * 4][c] = A[(size_t)(row0 + r + p * 4) * SEQ + k0 + c];
            Vs[r + p * 4][c] = V[(size_t)(k0 + r + p * 4) * DEPTH + c];
        }
        __syncthreads();

        #pragma unroll
        for (int kk = 0; kk < 64; kk++) {
            float a[4], vv[4];
            #pragma unroll
            for (int i = 0; i < 4; i++) a[i]  = As[ty * 4 + i][kk];
            #pragma unroll
            for (int j = 0; j < 4; j++) vv[j] = Vs[kk][tx * 4 + j];
            #pragma unroll
            for (int i = 0; i < 4; i++)
                #pragma unroll
                for (int j = 0; j < 4; j++)
                    acc[i][j] = fmaf(a[i], vv[j], acc[i][j]);
        }
        __syncthreads();
    }

    #pragma unroll
    for (int i = 0; i < 4; i++) {
        const size_t obase = (size_t)(b * SEQ + row0 + ty * 4 + i) * DMODEL + h * DEPTH;
        #pragma unroll
        for (int j = 0; j < 4; j++)
            g_ctx[obase + tx * 4 + j] = acc[i][j];
    }
}

// ---------------------------------------------------------------------------
// K5: out = ctx @ Wo + bo   (plain [ROWS, DMODEL] output)
// ---------------------------------------------------------------------------
__global__ __launch_bounds__(256) void out_gemm(
    const float* __restrict__ Wo, const float* __restrict__ bo,
    float* __restrict__ out)
{
    __shared__ float As[64][17];
    __shared__ float Bs[16][65];

    const int row0 = blockIdx.y * 64;
    const int col0 = blockIdx.x * 64;
    const int tid  = threadIdx.x;
    const int tx   = tid & 15;
    const int ty   = tid >> 4;

    float acc[4][4] = {};

    for (int k0 = 0; k0 < DMODEL; k0 += 16) {
        {
            const int c = tid & 15;
            const int r = tid >> 4;
            #pragma unroll
            for (int p = 0; p < 4; p++)
                As[r + p * 16][c] = g_ctx[(size_t)(row0 + r + p * 16) * DMODEL + k0 + c];
        }
        {
            const int c = tid & 63;
            const int r = tid >> 6;
            #pragma unroll
            for (int p = 0; p < 4; p++)
                Bs[r + p * 4][c] = Wo[(size_t)(k0 + r + p * 4) * DMODEL + col0 + c];
        }
        __syncthreads();

        #pragma unroll
        for (int kk = 0; kk < 16; kk++) {
            float a[4], bb[4];
            #pragma unroll
            for (int i = 0; i < 4; i++) a[i]  = As[ty * 4 + i][kk];
            #pragma unroll
            for (int j = 0; j < 4; j++) bb[j] = Bs[kk][tx * 4 + j];
            #pragma unroll
            for (int i = 0; i < 4; i++)
                #pragma unroll
                for (int j = 0; j < 4; j++)
                    acc[i][j] = fmaf(a[i], bb[j], acc[i][j]);
        }
        __syncthreads();
    }

    #pragma unroll
    for (int i = 0; i < 4; i++) {
        const size_t rbase = (size_t)(row0 + ty * 4 + i) * DMODEL + col0;
        #pragma unroll
        for (int j = 0; j < 4; j++)
            out[rbase + tx * 4 + j] = acc[i][j] + bo[col0 + tx * 4 + j];
    }
}

// ---------------------------------------------------------------------------
// Launch: output buffer = [out (B*S*D) | attn (B*H*S*S)]
// ---------------------------------------------------------------------------
extern "C" void kernel_launch(void* const* d_in, const int* in_sizes, int n_in,
                              void* d_out, int out_size)
{
    const float* x  = (const float*)d_in[0];
    const float* Wq = (const float*)d_in[1];
    const float* bq = (const float*)d_in[2];
    const float* Wk = (const float*)d_in[3];
    const float* bk = (const float*)d_in[4];
    const float* Wv = (const float*)d_in[5];
    const float* bv = (const float*)d_in[6];
    const float* Wo = (const float*)d_in[7];
    const float* bo = (const float*)d_in[8];

    float* out  = (float*)d_out;
    float* attn = out + (size_t)ROWS * DMODEL;

    dim3 g1(DMODEL / 64, ROWS / 64, 3);
    qkv_gemm<<<g1, 256>>>(x, Wq, bq, Wk, bk, Wv, bv);

    dim3 g2(SEQ / 64, SEQ / 64, BH);
    logits_kernel<<<g2, 256>>>(attn);

    softmax_kernel<<<BH * SEQ, 256>>>(attn);

    dim3 g4(1, SEQ / 64, BH);
    ctx_kernel<<<g4, 256>>>(attn);

    dim3 g5(DMODEL / 64, ROWS / 64, 1);
    out_gemm<<<g5, 256>>>(Wo, bo, out);
}

// round 2
// speedup vs baseline: 1.3060x; 1.3060x over previous
#include <cuda_runtime.h>
#include <cstdint>

#define BATCH  4
#define SEQ    2048
#define DMODEL 512
#define NHEAD  8
#define DEPTH  64
#define ROWS   (BATCH * SEQ)          // 8192
#define BH     (BATCH * NHEAD)        // 32
#define SCALE  0.125f                 // 1/sqrt(DEPTH)

// Scratch
__device__ float g_q[BH * SEQ * DEPTH];
__device__ float g_k[BH * SEQ * DEPTH];
__device__ float g_v[BH * SEQ * DEPTH];
__device__ float g_ctx[ROWS * DMODEL];
__device__ float g_rowsum[BH * SEQ];

// ---------------------------------------------------------------------------
// tf32 helpers
// ---------------------------------------------------------------------------
__device__ __forceinline__ uint32_t f2tf32(float x) {
    uint32_t r;
    asm("cvt.rna.tf32.f32 %0, %1;" : "=r"(r) : "f"(x));
    return r;
}
__device__ __forceinline__ void mma8(float* c,
                                     uint32_t a0, uint32_t a1, uint32_t a2, uint32_t a3,
                                     uint32_t b0, uint32_t b1) {
    asm("mma.sync.aligned.m16n8k8.row.col.f32.tf32.tf32.f32 "
        "{%0,%1,%2,%3},{%4,%5,%6,%7},{%8,%9},{%0,%1,%2,%3};"
        : "+f"(c[0]), "+f"(c[1]), "+f"(c[2]), "+f"(c[3])
        : "r"(a0), "r"(a1), "r"(a2), "r"(a3), "r"(b0), "r"(b1));
}

// ---------------------------------------------------------------------------
// K1: fused QKV projection (fp32 FMA, 128x64 tile, BK=16, 8x4 micro)
// grid: (512/64, 8192/128, 3), block 256
// ---------------------------------------------------------------------------
__global__ __launch_bounds__(256) void qkv_gemm(
    const float* __restrict__ x,
    const float* __restrict__ Wq, const float* __restrict__ bq,
    const float* __restrict__ Wk, const float* __restrict__ bk,
    const float* __restrict__ Wv, const float* __restrict__ bv)
{
    const float* W; const float* bias; float* out;
    if (blockIdx.z == 0)      { W = Wq; bias = bq; out = g_q; }
    else if (blockIdx.z == 1) { W = Wk; bias = bk; out = g_k; }
    else                      { W = Wv; bias = bv; out = g_v; }

    __shared__ float As[16][132];   // [k][m]
    __shared__ float Bs[16][68];    // [k][n]

    const int row0 = blockIdx.y * 128;
    const int col0 = blockIdx.x * 64;
    const int tid  = threadIdx.x;
    const int tx   = tid & 15;
    const int ty   = tid >> 4;

    float acc[8][4] = {};

    for (int k0 = 0; k0 < DMODEL; k0 += 16) {
        #pragma unroll
        for (int p = 0; p < 2; p++) {
            int idx = tid + p * 256;
            int row = idx >> 2, k4 = idx & 3;
            float4 v = *(const float4*)(x + (size_t)(row0 + row) * DMODEL + k0 + k4 * 4);
            As[k4 * 4 + 0][row] = v.x;
            As[k4 * 4 + 1][row] = v.y;
            As[k4 * 4 + 2][row] = v.z;
            As[k4 * 4 + 3][row] = v.w;
        }
        {
            int row = tid >> 4, c4 = tid & 15;
            *(float4*)(&Bs[row][c4 * 4]) =
                *(const float4*)(W + (size_t)(k0 + row) * DMODEL + col0 + c4 * 4);
        }
        __syncthreads();

        #pragma unroll
        for (int kk = 0; kk < 16; kk++) {
            float4 a0 = *(const float4*)(&As[kk][ty * 8]);
            float4 a1 = *(const float4*)(&As[kk][ty * 8 + 4]);
            float4 bv = *(const float4*)(&Bs[kk][tx * 4]);
            float a[8] = {a0.x, a0.y, a0.z, a0.w, a1.x, a1.y, a1.z, a1.w};
            float bb[4] = {bv.x, bv.y, bv.z, bv.w};
            #pragma unroll
            for (int i = 0; i < 8; i++)
                #pragma unroll
                for (int j = 0; j < 4; j++)
                    acc[i][j] = fmaf(a[i], bb[j], acc[i][j]);
        }
        __syncthreads();
    }

    #pragma unroll
    for (int i = 0; i < 8; i++) {
        const int row = row0 + ty * 8 + i;
        const int b   = row / SEQ;
        const int s   = row % SEQ;
        #pragma unroll
        for (int j = 0; j < 4; j++) {
            const int col = col0 + tx * 4 + j;
            const int h   = col >> 6;
            const int d   = col & 63;
            out[(size_t)((b * NHEAD + h) * SEQ + s) * DEPTH + d] = acc[i][j] + bias[col];
        }
    }
}

// ---------------------------------------------------------------------------
// K2: exp(logits) with split-tf32 mma + deterministic row sums.
// CTA = (qtile of 128 rows, bh). Loops over 32 k-col tiles of 64.
// Warps: 2 (m) x 4 (n); warp tile 64x16 per iter.
// ---------------------------------------------------------------------------
__global__ __launch_bounds__(256) void logits_exp_kernel(float* __restrict__ attn)
{
    extern __shared__ float sm[];
    float* Qs = sm;                    // [128][68]
    float* Ks = sm + 128 * 68;         // [64][68]
    float* rs = Ks + 64 * 68;          // [4][128]

    const int qrow0 = blockIdx.x * 128;
    const int bh    = blockIdx.y;
    const float* qg = g_q + (size_t)bh * SEQ * DEPTH;
    const float* kg = g_k + (size_t)bh * SEQ * DEPTH;
    float* outp     = attn + (size_t)bh * SEQ * SEQ;

    const int tid  = threadIdx.x;
    const int lane = tid & 31, wid = tid >> 5;
    const int wm = wid >> 2, wn = wid & 3;

    #pragma unroll
    for (int p = 0; p < 8; p++) {
        int idx = tid + p * 256;
        int row = idx >> 4, c4 = idx & 15;
        *(float4*)(Qs + row * 68 + c4 * 4) =
            *(const float4*)(qg + (size_t)(qrow0 + row) * DEPTH + c4 * 4);
    }

    float rowpart[8];
    #pragma unroll
    for (int i = 0; i < 8; i++) rowpart[i] = 0.f;

    const int rquad = lane >> 2;
    const int cquad = lane & 3;

    for (int it = 0; it < 32; it++) {
        const int kcol0 = it * 64;
        __syncthreads();
        #pragma unroll
        for (int p = 0; p < 4; p++) {
            int idx = tid + p * 256;
            int row = idx >> 4, c4 = idx & 15;
            *(float4*)(Ks + row * 68 + c4 * 4) =
                *(const float4*)(kg + (size_t)(kcol0 + row) * DEPTH + c4 * 4);
        }
        __syncthreads();

        float c[4][2][4] = {};
        #pragma unroll
        for (int ks = 0; ks < 8; ks++) {
            uint32_t ah[4][4], al[4][4];
            #pragma unroll
            for (int mi = 0; mi < 4; mi++) {
                const float* qp = Qs + (wm * 64 + mi * 16 + rquad) * 68 + ks * 8 + cquad;
                float a0 = qp[0], a1 = qp[8 * 68], a2 = qp[4], a3 = qp[8 * 68 + 4];
                ah[mi][0] = f2tf32(a0); al[mi][0] = f2tf32(a0 - __uint_as_float(ah[mi][0]));
                ah[mi][1] = f2tf32(a1); al[mi][1] = f2tf32(a1 - __uint_as_float(ah[mi][1]));
                ah[mi][2] = f2tf32(a2); al[mi][2] = f2tf32(a2 - __uint_as_float(ah[mi][2]));
                ah[mi][3] = f2tf32(a3); al[mi][3] = f2tf32(a3 - __uint_as_float(ah[mi][3]));
            }
            uint32_t bhh[2][2], bll[2][2];
            #pragma unroll
            for (int ni = 0; ni < 2; ni++) {
                const float* kp = Ks + (wn * 16 + ni * 8 + rquad) * 68 + ks * 8 + cquad;
                float b0 = kp[0], b1 = kp[4];
                bhh[ni][0] = f2tf32(b0); bll[ni][0] = f2tf32(b0 - __uint_as_float(bhh[ni][0]));
                bhh[ni][1] = f2tf32(b1); bll[ni][1] = f2tf32(b1 - __uint_as_float(bhh[ni][1]));
            }
            #pragma unroll
            for (int mi = 0; mi < 4; mi++)
                #pragma unroll
                for (int ni = 0; ni < 2; ni++) {
                    mma8(c[mi][ni], ah[mi][0], ah[mi][1], ah[mi][2], ah[mi][3], bhh[ni][0], bhh[ni][1]);
                    mma8(c[mi][ni], al[mi][0], al[mi][1], al[mi][2], al[mi][3], bhh[ni][0], bhh[ni][1]);
                    mma8(c[mi][ni], ah[mi][0], ah[mi][1], ah[mi][2], ah[mi][3], bll[ni][0], bll[ni][1]);
                }
        }

        // exp + store + rowsum partials
        #pragma unroll
        for (int mi = 0; mi < 4; mi++) {
            const int rA = qrow0 + wm * 64 + mi * 16 + rquad;
            #pragma unroll
            for (int ni = 0; ni < 2; ni++) {
                const int col = kcol0 + wn * 16 + ni * 8 + cquad * 2;
                float e0 = __expf(c[mi][ni][0] * SCALE);
                float e1 = __expf(c[mi][ni][1] * SCALE);
                float e2 = __expf(c[mi][ni][2] * SCALE);
                float e3 = __expf(c[mi][ni][3] * SCALE);
                rowpart[mi * 2 + 0] += e0 + e1;
                rowpart[mi * 2 + 1] += e2 + e3;
                *(float2*)(outp + (size_t)rA * SEQ + col)       = make_float2(e0, e1);
                *(float2*)(outp + (size_t)(rA + 8) * SEQ + col) = make_float2(e2, e3);
            }
        }
    }

    // deterministic row-sum reduction: quad shuffle, then across n-warps in SMEM
    #pragma unroll
    for (int i = 0; i < 8; i++) {
        float v = rowpart[i];
        v += __shfl_xor_sync(0xffffffffu, v, 1);
        v += __shfl_xor_sync(0xffffffffu, v, 2);
        if (cquad == 0) {
            int mi = i >> 1, half = i & 1;
            int rloc = wm * 64 + mi * 16 + half * 8 + rquad;
            rs[wn * 128 + rloc] = v;
        }
    }
    __syncthreads();
    if (tid < 128) {
        float s = rs[tid] + rs[128 + tid] + rs[256 + tid] + rs[384 + tid];
        g_rowsum[(size_t)bh * SEQ + qrow0 + tid] = s;
    }
}

// ---------------------------------------------------------------------------
// K3: ctx = norm(attn) @ v with split-tf32 mma; normalizes attn in place.
// CTA = (qtile of 128 rows, bh). Warps 4 (m) x 2 (n); warp tile 32x32.
// ---------------------------------------------------------------------------
__global__ __launch_bounds__(256) void ctx_norm_kernel(float* __restrict__ attn)
{
    extern __shared__ float sm[];
    float* As   = sm;                  // [128][68]
    float* Vs   = sm + 128 * 68;       // [64][72]
    float* invs = Vs + 64 * 72;        // [128]

    const int qrow0 = blockIdx.x * 128;
    const int bh    = blockIdx.y;
    const int b = bh >> 3, h = bh & 7;
    float* ap       = attn + (size_t)bh * SEQ * SEQ;
    const float* vg = g_v + (size_t)bh * SEQ * DEPTH;

    const int tid = threadIdx.x, lane = tid & 31, wid = tid >> 5;
    const int wm = wid >> 1, wn = wid & 1;
    const int rquad = lane >> 2, cquad = lane & 3;

    if (tid < 128)
        invs[tid] = 1.0f / g_rowsum[(size_t)bh * SEQ + qrow0 + tid];

    float c[2][4][4] = {};

    for (int it = 0; it < 32; it++) {
        const int s0 = it * 64;
        __syncthreads();
        #pragma unroll
        for (int p = 0; p < 8; p++) {
            int idx = tid + p * 256;
            int row = idx >> 4, c4 = idx & 15;
            float* gaddr = ap + (size_t)(qrow0 + row) * SEQ + s0 + c4 * 4;
            float4 v = *(const float4*)gaddr;
            float inv = invs[row];
            v.x *= inv; v.y *= inv; v.z *= inv; v.w *= inv;
            *(float4*)gaddr = v;                      // final normalized attn
            *(float4*)(As + row * 68 + c4 * 4) = v;
        }
        #pragma unroll
        for (int p = 0; p < 4; p++) {
            int idx = tid + p * 256;
            int row = idx >> 4, c4 = idx & 15;
            *(float4*)(Vs + row * 72 + c4 * 4) =
                *(const float4*)(vg + (size_t)(s0 + row) * DEPTH + c4 * 4);
        }
        __syncthreads();

        #pragma unroll
        for (int ks = 0; ks < 8; ks++) {
            uint32_t ah[2][4], al[2][4];
            #pragma unroll
            for (int mi = 0; mi < 2; mi++) {
                const float* apm = As + (wm * 32 + mi * 16 + rquad) * 68 + ks * 8 + cquad;
                float a0 = apm[0], a1 = apm[8 * 68], a2 = apm[4], a3 = apm[8 * 68 + 4];
                ah[mi][0] = f2tf32(a0); al[mi][0] = f2tf32(a0 - __uint_as_float(ah[mi][0]));
                ah[mi][1] = f2tf32(a1); al[mi][1] = f2tf32(a1 - __uint_as_float(ah[mi][1]));
                ah[mi][2] = f2tf32(a2); al[mi][2] = f2tf32(a2 - __uint_as_float(ah[mi][2]));
                ah[mi][3] = f2tf32(a3); al[mi][3] = f2tf32(a3 - __uint_as_float(ah[mi][3]));
            }
            uint32_t bhh[4][2], bll[4][2];
            #pragma unroll
            for (int ni = 0; ni < 4; ni++) {
                const int cb = wn * 32 + ni * 8 + rquad;
                float b0 = Vs[(ks * 8 + cquad) * 72 + cb];
                float b1 = Vs[(ks * 8 + cquad + 4) * 72 + cb];
                bhh[ni][0] = f2tf32(b0); bll[ni][0] = f2tf32(b0 - __uint_as_float(bhh[ni][0]));
                bhh[ni][1] = f2tf32(b1); bll[ni][1] = f2tf32(b1 - __uint_as_float(bhh[ni][1]));
            }
            #pragma unroll
            for (int mi = 0; mi < 2; mi++)
                #pragma unroll
                for (int ni = 0; ni < 4; ni++) {
                    mma8(c[mi][ni], ah[mi][0], ah[mi][1], ah[mi][2], ah[mi][3], bhh[ni][0], bhh[ni][1]);
                    mma8(c[mi][ni], al[mi][0], al[mi][1], al[mi][2], al[mi][3], bhh[ni][0], bhh[ni][1]);
                    mma8(c[mi][ni], ah[mi][0], ah[mi][1], ah[mi][2], ah[mi][3], bll[ni][0], bll[ni][1]);
                }
        }
    }

    #pragma unroll
    for (int mi = 0; mi < 2; mi++)
        #pragma unroll
        for (int ni = 0; ni < 4; ni++) {
            const int r   = qrow0 + wm * 32 + mi * 16 + rquad;
            const int col = h * 64 + wn * 32 + ni * 8 + cquad * 2;
            *(float2*)(g_ctx + (size_t)(b * SEQ + r) * DMODEL + col) =
                make_float2(c[mi][ni][0], c[mi][ni][1]);
            *(float2*)(g_ctx + (size_t)(b * SEQ + r + 8) * DMODEL + col) =
                make_float2(c[mi][ni][2], c[mi][ni][3]);
        }
}

// ---------------------------------------------------------------------------
// K4: out = ctx @ Wo + bo (fp32 FMA, same tiling as K1)
// ---------------------------------------------------------------------------
__global__ __launch_bounds__(256) void out_gemm(
    const float* __restrict__ Wo, const float* __restrict__ bo,
    float* __restrict__ out)
{
    __shared__ float As[16][132];
    __shared__ float Bs[16][68];

    const int row0 = blockIdx.y * 128;
    const int col0 = blockIdx.x * 64;
    const int tid  = threadIdx.x;
    const int tx   = tid & 15;
    const int ty   = tid >> 4;

    float acc[8][4] = {};

    for (int k0 = 0; k0 < DMODEL; k0 += 16) {
        #pragma unroll
        for (int p = 0; p < 2; p++) {
            int idx = tid + p * 256;
            int row = idx >> 2, k4 = idx & 3;
            float4 v = *(const float4*)(g_ctx + (size_t)(row0 + row) * DMODEL + k0 + k4 * 4);
            As[k4 * 4 + 0][row] = v.x;
            As[k4 * 4 + 1][row] = v.y;
            As[k4 * 4 + 2][row] = v.z;
            As[k4 * 4 + 3][row] = v.w;
        }
        {
            int row = tid >> 4, c4 = tid & 15;
            *(float4*)(&Bs[row][c4 * 4]) =
                *(const float4*)(Wo + (size_t)(k0 + row) * DMODEL + col0 + c4 * 4);
        }
        __syncthreads();

        #pragma unroll
        for (int kk = 0; kk < 16; kk++) {
            float4 a0 = *(const float4*)(&As[kk][ty * 8]);
            float4 a1 = *(const float4*)(&As[kk][ty * 8 + 4]);
            float4 bv = *(const float4*)(&Bs[kk][tx * 4]);
            float a[8] = {a0.x, a0.y, a0.z, a0.w, a1.x, a1.y, a1.z, a1.w};
            float bb[4] = {bv.x, bv.y, bv.z, bv.w};
            #pragma unroll
            for (int i = 0; i < 8; i++)
                #pragma unroll
                for (int j = 0; j < 4; j++)
                    acc[i][j] = fmaf(a[i], bb[j], acc[i][j]);
        }
        __syncthreads();
    }

    #pragma unroll
    for (int i = 0; i < 8; i++) {
        const size_t rbase = (size_t)(row0 + ty * 8 + i) * DMODEL + col0;
        #pragma unroll
        for (int j = 0; j < 4; j++)
            out[rbase + tx * 4 + j] = acc[i][j] + bo[col0 + tx * 4 + j];
    }
}

// ---------------------------------------------------------------------------
extern "C" void kernel_launch(void* const* d_in, const int* in_sizes, int n_in,
                              void* d_out, int out_size)
{
    const float* x  = (const float*)d_in[0];
    const float* Wq = (const float*)d_in[1];
    const float* bq = (const float*)d_in[2];
    const float* Wk = (const float*)d_in[3];
    const float* bk = (const float*)d_in[4];
    const float* Wv = (const float*)d_in[5];
    const float* bv = (const float*)d_in[6];
    const float* Wo = (const float*)d_in[7];
    const float* bo = (const float*)d_in[8];

    float* out  = (float*)d_out;
    float* attn = out + (size_t)ROWS * DMODEL;

    const int smem_k2 = (128 * 68 + 64 * 68 + 4 * 128) * 4;   // 54272
    const int smem_k3 = (128 * 68 + 64 * 72 + 128) * 4;       // 53760
    cudaFuncSetAttribute(logits_exp_kernel, cudaFuncAttributeMaxDynamicSharedMemorySize, smem_k2);
    cudaFuncSetAttribute(ctx_norm_kernel,   cudaFuncAttributeMaxDynamicSharedMemorySize, smem_k3);

    qkv_gemm<<<dim3(DMODEL / 64, ROWS / 128, 3), 256>>>(x, Wq, bq, Wk, bk, Wv, bv);
    logits_exp_kernel<<<dim3(SEQ / 128, BH), 256, smem_k2>>>(attn);
    ctx_norm_kernel<<<dim3(SEQ / 128, BH), 256, smem_k3>>>(attn);
    out_gemm<<<dim3(DMODEL / 64, ROWS / 128), 256>>>(Wo, bo, out);
}

// round 4
// speedup vs baseline: 2.1039x; 1.6110x over previous
#include <cuda_runtime.h>
#include <cstdint>

#define BATCH  4
#define SEQ    2048
#define DMODEL 512
#define NHEAD  8
#define DEPTH  64
#define ROWS   (BATCH * SEQ)          // 8192
#define BH     (BATCH * NHEAD)        // 32
#define SCALE  0.125f                 // 1/sqrt(DEPTH)

// Scratch
__device__ float g_q[BH * SEQ * DEPTH];     // tf32-rounded values
__device__ float g_k[BH * SEQ * DEPTH];     // tf32-rounded values
__device__ float g_v[BH * SEQ * DEPTH];     // tf32-rounded values
__device__ float g_ctx[ROWS * DMODEL];
__device__ float g_rowsum[BH * SEQ];

// ---------------------------------------------------------------------------
// tf32 helpers
// ---------------------------------------------------------------------------
__device__ __forceinline__ uint32_t f2tf32(float x) {
    uint32_t r;
    asm("cvt.rna.tf32.f32 %0, %1;" : "=r"(r) : "f"(x));
    return r;
}
__device__ __forceinline__ void mma8(float* c,
                                     uint32_t a0, uint32_t a1, uint32_t a2, uint32_t a3,
                                     uint32_t b0, uint32_t b1) {
    asm("mma.sync.aligned.m16n8k8.row.col.f32.tf32.tf32.f32 "
        "{%0,%1,%2,%3},{%4,%5,%6,%7},{%8,%9},{%0,%1,%2,%3};"
        : "+f"(c[0]), "+f"(c[1]), "+f"(c[2]), "+f"(c[3])
        : "r"(a0), "r"(a1), "r"(a2), "r"(a3), "r"(b0), "r"(b1));
}

// ---------------------------------------------------------------------------
// K1: generic tf32 GEMM, C[128-tile, 64-tile] = A[.,512] @ W[512,.] + bias
// MODE 0: qkv (A = x; blockIdx.z selects weight; head-split write; tf32 out)
// MODE 1: output projection (A = g_ctx device symbol; plain write)
// Block 256 = 8 warps (4m x 2n); tile 128x64, BK=32; warp tile 32x32.
// ---------------------------------------------------------------------------
template<int MODE>
__global__ __launch_bounds__(256) void gemm_tf32(
    const float* __restrict__ A,
    const float* __restrict__ Wq, const float* __restrict__ bq,
    const float* __restrict__ Wk, const float* __restrict__ bk,
    const float* __restrict__ Wv, const float* __restrict__ bv,
    float* __restrict__ outp)
{
    const float* W; const float* bias; float* out;
    const float* Asrc;
    if (MODE == 0) {
        Asrc = A;
        if (blockIdx.z == 0)      { W = Wq; bias = bq; out = g_q; }
        else if (blockIdx.z == 1) { W = Wk; bias = bk; out = g_k; }
        else                      { W = Wv; bias = bv; out = g_v; }
    } else {
        Asrc = g_ctx;            // device-side symbol reference (host addr invalid!)
        W = Wq; bias = bq; out = outp;
    }

    __shared__ float As[128 * 36];   // [m][k], stride 36
    __shared__ float Bs[32 * 68];    // [k][n], stride 68

    const int row0 = blockIdx.y * 128;
    const int col0 = blockIdx.x * 64;
    const int tid  = threadIdx.x;
    const int lane = tid & 31, wid = tid >> 5;
    const int wm = wid >> 1, wn = wid & 1;
    const int rquad = lane >> 2, cquad = lane & 3;

    float c[2][4][4] = {};

    for (int k0 = 0; k0 < DMODEL; k0 += 32) {
        // stage A tile 128x32 (round to tf32)
        #pragma unroll
        for (int p = 0; p < 4; p++) {
            int idx = tid + p * 256;
            int row = idx >> 3, kg = idx & 7;
            float4 v = *(const float4*)(Asrc + (size_t)(row0 + row) * DMODEL + k0 + kg * 4);
            v.x = __uint_as_float(f2tf32(v.x));
            v.y = __uint_as_float(f2tf32(v.y));
            v.z = __uint_as_float(f2tf32(v.z));
            v.w = __uint_as_float(f2tf32(v.w));
            *(float4*)(As + row * 36 + kg * 4) = v;
        }
        // stage B tile 32x64 (round to tf32)
        #pragma unroll
        for (int p = 0; p < 2; p++) {
            int idx = tid + p * 256;
            int row = idx >> 4, c4 = idx & 15;
            float4 v = *(const float4*)(W + (size_t)(k0 + row) * DMODEL + col0 + c4 * 4);
            v.x = __uint_as_float(f2tf32(v.x));
            v.y = __uint_as_float(f2tf32(v.y));
            v.z = __uint_as_float(f2tf32(v.z));
            v.w = __uint_as_float(f2tf32(v.w));
            *(float4*)(Bs + row * 68 + c4 * 4) = v;
        }
        __syncthreads();

        #pragma unroll
        for (int ks = 0; ks < 4; ks++) {
            uint32_t a[2][4];
            #pragma unroll
            for (int mi = 0; mi < 2; mi++) {
                const float* ap = As + (wm * 32 + mi * 16 + rquad) * 36 + ks * 8 + cquad;
                a[mi][0] = __float_as_uint(ap[0]);
                a[mi][1] = __float_as_uint(ap[8 * 36]);
                a[mi][2] = __float_as_uint(ap[4]);
                a[mi][3] = __float_as_uint(ap[8 * 36 + 4]);
            }
            uint32_t b[4][2];
            #pragma unroll
            for (int ni = 0; ni < 4; ni++) {
                const float* bp = Bs + (ks * 8 + cquad) * 68 + wn * 32 + ni * 8 + rquad;
                b[ni][0] = __float_as_uint(bp[0]);
                b[ni][1] = __float_as_uint(bp[4 * 68]);
            }
            #pragma unroll
            for (int mi = 0; mi < 2; mi++)
                #pragma unroll
                for (int ni = 0; ni < 4; ni++)
                    mma8(c[mi][ni], a[mi][0], a[mi][1], a[mi][2], a[mi][3],
                         b[ni][0], b[ni][1]);
        }
        __syncthreads();
    }

    // epilogue
    #pragma unroll
    for (int mi = 0; mi < 2; mi++) {
        const int r = row0 + wm * 32 + mi * 16 + rquad;
        #pragma unroll
        for (int ni = 0; ni < 4; ni++) {
            const int col = col0 + wn * 32 + ni * 8 + cquad * 2;
            float v0 = c[mi][ni][0] + bias[col];
            float v1 = c[mi][ni][1] + bias[col + 1];
            float v2 = c[mi][ni][2] + bias[col];
            float v3 = c[mi][ni][3] + bias[col + 1];
            if (MODE == 0) {
                v0 = __uint_as_float(f2tf32(v0));
                v1 = __uint_as_float(f2tf32(v1));
                v2 = __uint_as_float(f2tf32(v2));
                v3 = __uint_as_float(f2tf32(v3));
                const int h = col >> 6;          // col0 multiple of 64 -> single h
                const int d = col & 63;
                const int b0 = r / SEQ, s0 = r % SEQ;
                float* o0 = out + (size_t)((b0 * NHEAD + h) * SEQ + s0) * DEPTH + d;
                *(float2*)o0 = make_float2(v0, v1);
                const int b1 = (r + 8) / SEQ, s1 = (r + 8) % SEQ;
                float* o1 = out + (size_t)((b1 * NHEAD + h) * SEQ + s1) * DEPTH + d;
                *(float2*)o1 = make_float2(v2, v3);
            } else {
                *(float2*)(out + (size_t)r * DMODEL + col)       = make_float2(v0, v1);
                *(float2*)(out + (size_t)(r + 8) * DMODEL + col) = make_float2(v2, v3);
            }
        }
    }
}

// ---------------------------------------------------------------------------
// K2: attn_raw = exp(q@k^T * SCALE), rowsums. Q held in registers.
// Block 256 (4m x 2n warps); CTA: 128 q-rows x full SEQ (32 iters of 64 cols).
// ---------------------------------------------------------------------------
__global__ __launch_bounds__(256) void logits_exp_kernel(float* __restrict__ attn)
{
    __shared__ float S[128 * 68];   // Q staging, then K tiles
    __shared__ float rs[256];

    const int qrow0 = blockIdx.x * 128;
    const int bh    = blockIdx.y;
    const float* qg = g_q + (size_t)bh * SEQ * DEPTH;
    const float* kg = g_k + (size_t)bh * SEQ * DEPTH;
    float* outp     = attn + (size_t)bh * SEQ * SEQ;

    const int tid  = threadIdx.x;
    const int lane = tid & 31, wid = tid >> 5;
    const int wm = wid >> 1, wn = wid & 1;
    const int rquad = lane >> 2, cquad = lane & 3;

    // stage Q tile 128x64 (already tf32-rounded)
    #pragma unroll
    for (int p = 0; p < 8; p++) {
        int idx = tid + p * 256;
        int row = idx >> 4, c4 = idx & 15;
        *(float4*)(S + row * 68 + c4 * 4) =
            *(const float4*)(qg + (size_t)(qrow0 + row) * DEPTH + c4 * 4);
    }
    __syncthreads();

    // extract Q fragments to registers (rows wm*32..+31, full k=64)
    uint32_t qa[2][8][4];
    #pragma unroll
    for (int mi = 0; mi < 2; mi++)
        #pragma unroll
        for (int ks = 0; ks < 8; ks++) {
            const float* qp = S + (wm * 32 + mi * 16 + rquad) * 68 + ks * 8 + cquad;
            qa[mi][ks][0] = __float_as_uint(qp[0]);
            qa[mi][ks][1] = __float_as_uint(qp[8 * 68]);
            qa[mi][ks][2] = __float_as_uint(qp[4]);
            qa[mi][ks][3] = __float_as_uint(qp[8 * 68 + 4]);
        }
    __syncthreads();

    float rowpart[4] = {0.f, 0.f, 0.f, 0.f};

    for (int it = 0; it < 32; it++) {
        const int kcol0 = it * 64;
        // stage K tile 64x64
        #pragma unroll
        for (int p = 0; p < 4; p++) {
            int idx = tid + p * 256;
            int row = idx >> 4, c4 = idx & 15;
            *(float4*)(S + row * 68 + c4 * 4) =
                *(const float4*)(kg + (size_t)(kcol0 + row) * DEPTH + c4 * 4);
        }
        __syncthreads();

        float c[2][4][4] = {};
        #pragma unroll
        for (int ks = 0; ks < 8; ks++) {
            uint32_t b[4][2];
            #pragma unroll
            for (int ni = 0; ni < 4; ni++) {
                const float* kp = S + (wn * 32 + ni * 8 + rquad) * 68 + ks * 8 + cquad;
                b[ni][0] = __float_as_uint(kp[0]);
                b[ni][1] = __float_as_uint(kp[4]);
            }
            #pragma unroll
            for (int mi = 0; mi < 2; mi++)
                #pragma unroll
                for (int ni = 0; ni < 4; ni++)
                    mma8(c[mi][ni], qa[mi][ks][0], qa[mi][ks][1], qa[mi][ks][2], qa[mi][ks][3],
                         b[ni][0], b[ni][1]);
        }

        // exp + store + rowsum partials
        #pragma unroll
        for (int mi = 0; mi < 2; mi++) {
            const int rA = qrow0 + wm * 32 + mi * 16 + rquad;
            #pragma unroll
            for (int ni = 0; ni < 4; ni++) {
                const int col = kcol0 + wn * 32 + ni * 8 + cquad * 2;
                float e0 = __expf(c[mi][ni][0] * SCALE);
                float e1 = __expf(c[mi][ni][1] * SCALE);
                float e2 = __expf(c[mi][ni][2] * SCALE);
                float e3 = __expf(c[mi][ni][3] * SCALE);
                rowpart[mi * 2 + 0] += e0 + e1;
                rowpart[mi * 2 + 1] += e2 + e3;
                *(float2*)(outp + (size_t)rA * SEQ + col)       = make_float2(e0, e1);
                *(float2*)(outp + (size_t)(rA + 8) * SEQ + col) = make_float2(e2, e3);
            }
        }
        __syncthreads();
    }

    // deterministic rowsum reduction
    #pragma unroll
    for (int i = 0; i < 4; i++) {
        float v = rowpart[i];
        v += __shfl_xor_sync(0xffffffffu, v, 1);
        v += __shfl_xor_sync(0xffffffffu, v, 2);
        if (cquad == 0) {
            int rloc = wm * 32 + (i >> 1) * 16 + (i & 1) * 8 + rquad;
            rs[wn * 128 + rloc] = v;
        }
    }
    __syncthreads();
    if (tid < 128)
        g_rowsum[(size_t)bh * SEQ + qrow0 + tid] = rs[tid] + rs[128 + tid];
}

// ---------------------------------------------------------------------------
// K3: normalize attn in place + ctx = attn_norm @ v.
// Block 256 (4m x 2n warps); CTA: 128 q-rows x DEPTH out; 32 iters of 64 k.
// ---------------------------------------------------------------------------
__global__ __launch_bounds__(256) void ctx_norm_kernel(float* __restrict__ attn)
{
    extern __shared__ float sm[];
    float* As   = sm;                  // [128][68]
    float* Vs   = sm + 128 * 68;       // [64][68]
    float* invs = Vs + 64 * 68;        // [128]

    const int qrow0 = blockIdx.x * 128;
    const int bh    = blockIdx.y;
    const int b = bh >> 3, h = bh & 7;
    float* ap       = attn + (size_t)bh * SEQ * SEQ;
    const float* vg = g_v + (size_t)bh * SEQ * DEPTH;

    const int tid = threadIdx.x, lane = tid & 31, wid = tid >> 5;
    const int wm = wid >> 1, wn = wid & 1;
    const int rquad = lane >> 2, cquad = lane & 3;

    if (tid < 128)
        invs[tid] = 1.0f / g_rowsum[(size_t)bh * SEQ + qrow0 + tid];
    __syncthreads();

    float c[2][4][4] = {};

    for (int it = 0; it < 32; it++) {
        const int s0 = it * 64;
        // stage attn tile: normalize, write back final attn, round into SMEM
        #pragma unroll
        for (int p = 0; p < 8; p++) {
            int idx = tid + p * 256;
            int row = idx >> 4, c4 = idx & 15;
            float* gaddr = ap + (size_t)(qrow0 + row) * SEQ + s0 + c4 * 4;
            float4 v = *(const float4*)gaddr;
            const float inv = invs[row];
            v.x *= inv; v.y *= inv; v.z *= inv; v.w *= inv;
            *(float4*)gaddr = v;
            float4 rv;
            rv.x = __uint_as_float(f2tf32(v.x));
            rv.y = __uint_as_float(f2tf32(v.y));
            rv.z = __uint_as_float(f2tf32(v.z));
            rv.w = __uint_as_float(f2tf32(v.w));
            *(float4*)(As + row * 68 + c4 * 4) = rv;
        }
        // stage V tile 64x64 (pre-rounded)
        #pragma unroll
        for (int p = 0; p < 4; p++) {
            int idx = tid + p * 256;
            int row = idx >> 4, c4 = idx & 15;
            *(float4*)(Vs + row * 68 + c4 * 4) =
                *(const float4*)(vg + (size_t)(s0 + row) * DEPTH + c4 * 4);
        }
        __syncthreads();

        #pragma unroll
        for (int ks = 0; ks < 8; ks++) {
            uint32_t a[2][4];
            #pragma unroll
            for (int mi = 0; mi < 2; mi++) {
                const float* apm = As + (wm * 32 + mi * 16 + rquad) * 68 + ks * 8 + cquad;
                a[mi][0] = __float_as_uint(apm[0]);
                a[mi][1] = __float_as_uint(apm[8 * 68]);
                a[mi][2] = __float_as_uint(apm[4]);
                a[mi][3] = __float_as_uint(apm[8 * 68 + 4]);
            }
            uint32_t bb[4][2];
            #pragma unroll
            for (int ni = 0; ni < 4; ni++) {
                const float* vp = Vs + (ks * 8 + cquad) * 68 + wn * 32 + ni * 8 + rquad;
                bb[ni][0] = __float_as_uint(vp[0]);
                bb[ni][1] = __float_as_uint(vp[4 * 68]);
            }
            #pragma unroll
            for (int mi = 0; mi < 2; mi++)
                #pragma unroll
                for (int ni = 0; ni < 4; ni++)
                    mma8(c[mi][ni], a[mi][0], a[mi][1], a[mi][2], a[mi][3],
                         bb[ni][0], bb[ni][1]);
        }
        __syncthreads();
    }

    // write ctx
    #pragma unroll
    for (int mi = 0; mi < 2; mi++) {
        const int r = qrow0 + wm * 32 + mi * 16 + rquad;
        #pragma unroll
        for (int ni = 0; ni < 4; ni++) {
            const int col = h * 64 + wn * 32 + ni * 8 + cquad * 2;
            *(float2*)(g_ctx + (size_t)(b * SEQ + r) * DMODEL + col) =
                make_float2(c[mi][ni][0], c[mi][ni][1]);
            *(float2*)(g_ctx + (size_t)(b * SEQ + r + 8) * DMODEL + col) =
                make_float2(c[mi][ni][2], c[mi][ni][3]);
        }
    }
}

// ---------------------------------------------------------------------------
extern "C" void kernel_launch(void* const* d_in, const int* in_sizes, int n_in,
                              void* d_out, int out_size)
{
    const float* x  = (const float*)d_in[0];
    const float* Wq = (const float*)d_in[1];
    const float* bq = (const float*)d_in[2];
    const float* Wk = (const float*)d_in[3];
    const float* bk = (const float*)d_in[4];
    const float* Wv = (const float*)d_in[5];
    const float* bv = (const float*)d_in[6];
    const float* Wo = (const float*)d_in[7];
    const float* bo = (const float*)d_in[8];

    float* out  = (float*)d_out;
    float* attn = out + (size_t)ROWS * DMODEL;

    const int smem_k3 = (128 * 68 + 64 * 68 + 128) * 4;   // 52736
    cudaFuncSetAttribute(ctx_norm_kernel, cudaFuncAttributeMaxDynamicSharedMemorySize, smem_k3);

    gemm_tf32<0><<<dim3(DMODEL / 64, ROWS / 128, 3), 256>>>(
        x, Wq, bq, Wk, bk, Wv, bv, nullptr);
    logits_exp_kernel<<<dim3(SEQ / 128, BH), 256>>>(attn);
    ctx_norm_kernel<<<dim3(SEQ / 128, BH), 256, smem_k3>>>(attn);
    gemm_tf32<1><<<dim3(DMODEL / 64, ROWS / 128, 1), 256>>>(
        nullptr, Wo, bo, nullptr, nullptr, nullptr, nullptr, out);
}

// round 5
// speedup vs baseline: 2.6236x; 1.2470x over previous
#include <cuda_runtime.h>
#include <cstdint>

#define BATCH  4
#define SEQ    2048
#define DMODEL 512
#define NHEAD  8
#define DEPTH  64
#define ROWS   (BATCH * SEQ)          // 8192
#define BH     (BATCH * NHEAD)        // 32
#define SCALE  0.125f                 // 1/sqrt(DEPTH), exact power of 2

// Scratch
__device__ float g_q[BH * SEQ * DEPTH];     // tf32-rounded
__device__ float g_k[BH * SEQ * DEPTH];     // tf32-rounded
__device__ float g_v[BH * SEQ * DEPTH];     // tf32-rounded
__device__ float g_ctx[ROWS * DMODEL];
__device__ float g_rowsum[BH * SEQ];

__device__ __forceinline__ uint32_t f2tf32(float x) {
    uint32_t r;
    asm("cvt.rna.tf32.f32 %0, %1;" : "=r"(r) : "f"(x));
    return r;
}
__device__ __forceinline__ void mma8(float* c,
                                     uint32_t a0, uint32_t a1, uint32_t a2, uint32_t a3,
                                     uint32_t b0, uint32_t b1) {
    asm("mma.sync.aligned.m16n8k8.row.col.f32.tf32.tf32.f32 "
        "{%0,%1,%2,%3},{%4,%5,%6,%7},{%8,%9},{%0,%1,%2,%3};"
        : "+f"(c[0]), "+f"(c[1]), "+f"(c[2]), "+f"(c[3])
        : "r"(a0), "r"(a1), "r"(a2), "r"(a3), "r"(b0), "r"(b1));
}

// ---------------------------------------------------------------------------
// K1: tf32 GEMM with 2-stage pipeline. C[128,64] tiles = A[.,512]@W[512,.]+b
// MODE 0: qkv (head-split, tf32-rounded out). MODE 1: out proj (A = g_ctx).
// 8 warps (4m x 2n), warp tile 32x32, BK=32, 16 k-iters.
// ---------------------------------------------------------------------------
template<int MODE>
__global__ __launch_bounds__(256) void gemm_tf32(
    const float* __restrict__ A,
    const float* __restrict__ Wq, const float* __restrict__ bq,
    const float* __restrict__ Wk, const float* __restrict__ bk,
    const float* __restrict__ Wv, const float* __restrict__ bv,
    float* __restrict__ outp)
{
    extern __shared__ float psm[];
    float* Asb = psm;                 // [2][128*36]
    float* Bsb = psm + 2 * 128 * 36;  // [2][32*68]

    const float* W; const float* bias; float* out;
    const float* Asrc;
    if (MODE == 0) {
        Asrc = A;
        if (blockIdx.z == 0)      { W = Wq; bias = bq; out = g_q; }
        else if (blockIdx.z == 1) { W = Wk; bias = bk; out = g_k; }
        else                      { W = Wv; bias = bv; out = g_v; }
    } else {
        Asrc = g_ctx;    // device-side symbol reference
        W = Wq; bias = bq; out = outp;
    }

    const int row0 = blockIdx.y * 128;
    const int col0 = blockIdx.x * 64;
    const int tid  = threadIdx.x;
    const int lane = tid & 31, wid = tid >> 5;
    const int wm = wid >> 1, wn = wid & 1;
    const int rquad = lane >> 2, cquad = lane & 3;

    // prefetch index precompute
    const int a_r = tid >> 3, a_kg = tid & 7;      // +p*32 rows
    const int b_r = tid >> 4, b_c4 = tid & 15;     // +p*16 rows

    float4 pa[4], pb[2];
    float c[2][4][4] = {};

    // prologue: tile 0
    #pragma unroll
    for (int p = 0; p < 4; p++)
        pa[p] = *(const float4*)(Asrc + (size_t)(row0 + a_r + p * 32) * DMODEL + a_kg * 4);
    #pragma unroll
    for (int p = 0; p < 2; p++)
        pb[p] = *(const float4*)(W + (size_t)(b_r + p * 16) * DMODEL + col0 + b_c4 * 4);
    #pragma unroll
    for (int p = 0; p < 4; p++) {
        float4 v = pa[p];
        v.x = __uint_as_float(f2tf32(v.x)); v.y = __uint_as_float(f2tf32(v.y));
        v.z = __uint_as_float(f2tf32(v.z)); v.w = __uint_as_float(f2tf32(v.w));
        *(float4*)(Asb + (a_r + p * 32) * 36 + a_kg * 4) = v;
    }
    #pragma unroll
    for (int p = 0; p < 2; p++) {
        float4 v = pb[p];
        v.x = __uint_as_float(f2tf32(v.x)); v.y = __uint_as_float(f2tf32(v.y));
        v.z = __uint_as_float(f2tf32(v.z)); v.w = __uint_as_float(f2tf32(v.w));
        *(float4*)(Bsb + (b_r + p * 16) * 68 + b_c4 * 4) = v;
    }

    for (int it = 0; it < 16; it++) {
        __syncthreads();
        if (it + 1 < 16) {
            const int k0 = (it + 1) * 32;
            #pragma unroll
            for (int p = 0; p < 4; p++)
                pa[p] = *(const float4*)(Asrc + (size_t)(row0 + a_r + p * 32) * DMODEL + k0 + a_kg * 4);
            #pragma unroll
            for (int p = 0; p < 2; p++)
                pb[p] = *(const float4*)(W + (size_t)(k0 + b_r + p * 16) * DMODEL + col0 + b_c4 * 4);
        }
        const float* As = Asb + (it & 1) * (128 * 36);
        const float* Bs = Bsb + (it & 1) * (32 * 68);
        #pragma unroll
        for (int ks = 0; ks < 4; ks++) {
            uint32_t a[2][4];
            #pragma unroll
            for (int mi = 0; mi < 2; mi++) {
                const float* ap = As + (wm * 32 + mi * 16 + rquad) * 36 + ks * 8 + cquad;
                a[mi][0] = __float_as_uint(ap[0]);
                a[mi][1] = __float_as_uint(ap[8 * 36]);
                a[mi][2] = __float_as_uint(ap[4]);
                a[mi][3] = __float_as_uint(ap[8 * 36 + 4]);
            }
            uint32_t b[4][2];
            #pragma unroll
            for (int ni = 0; ni < 4; ni++) {
                const float* bp = Bs + (ks * 8 + cquad) * 68 + wn * 32 + ni * 8 + rquad;
                b[ni][0] = __float_as_uint(bp[0]);
                b[ni][1] = __float_as_uint(bp[4 * 68]);
            }
            #pragma unroll
            for (int mi = 0; mi < 2; mi++)
                #pragma unroll
                for (int ni = 0; ni < 4; ni++)
                    mma8(c[mi][ni], a[mi][0], a[mi][1], a[mi][2], a[mi][3],
                         b[ni][0], b[ni][1]);
        }
        if (it + 1 < 16) {
            float* Asn = Asb + ((it + 1) & 1) * (128 * 36);
            float* Bsn = Bsb + ((it + 1) & 1) * (32 * 68);
            #pragma unroll
            for (int p = 0; p < 4; p++) {
                float4 v = pa[p];
                v.x = __uint_as_float(f2tf32(v.x)); v.y = __uint_as_float(f2tf32(v.y));
                v.z = __uint_as_float(f2tf32(v.z)); v.w = __uint_as_float(f2tf32(v.w));
                *(float4*)(Asn + (a_r + p * 32) * 36 + a_kg * 4) = v;
            }
            #pragma unroll
            for (int p = 0; p < 2; p++) {
                float4 v = pb[p];
                v.x = __uint_as_float(f2tf32(v.x)); v.y = __uint_as_float(f2tf32(v.y));
                v.z = __uint_as_float(f2tf32(v.z)); v.w = __uint_as_float(f2tf32(v.w));
                *(float4*)(Bsn + (b_r + p * 16) * 68 + b_c4 * 4) = v;
            }
        }
    }

    // epilogue
    #pragma unroll
    for (int mi = 0; mi < 2; mi++) {
        const int r = row0 + wm * 32 + mi * 16 + rquad;
        #pragma unroll
        for (int ni = 0; ni < 4; ni++) {
            const int col = col0 + wn * 32 + ni * 8 + cquad * 2;
            float v0 = c[mi][ni][0] + bias[col];
            float v1 = c[mi][ni][1] + bias[col + 1];
            float v2 = c[mi][ni][2] + bias[col];
            float v3 = c[mi][ni][3] + bias[col + 1];
            if (MODE == 0) {
                v0 = __uint_as_float(f2tf32(v0));
                v1 = __uint_as_float(f2tf32(v1));
                v2 = __uint_as_float(f2tf32(v2));
                v3 = __uint_as_float(f2tf32(v3));
                const int h = col >> 6;
                const int d = col & 63;
                const int b0 = r / SEQ, s0 = r % SEQ;
                *(float2*)(out + (size_t)((b0 * NHEAD + h) * SEQ + s0) * DEPTH + d) =
                    make_float2(v0, v1);
                const int b1 = (r + 8) / SEQ, s1 = (r + 8) % SEQ;
                *(float2*)(out + (size_t)((b1 * NHEAD + h) * SEQ + s1) * DEPTH + d) =
                    make_float2(v2, v3);
            } else {
                *(float2*)(out + (size_t)r * DMODEL + col)       = make_float2(v0, v1);
                *(float2*)(out + (size_t)(r + 8) * DMODEL + col) = make_float2(v2, v3);
            }
        }
    }
}

// ---------------------------------------------------------------------------
// K2: attn_raw = exp((q*SCALE)@k^T), rowsums. Q in registers (SCALE folded).
// 128 q-rows/CTA, 32 k-tiles of 64 cols, double-buffered K in reused SMEM.
// ---------------------------------------------------------------------------
__global__ __launch_bounds__(256) void logits_exp_kernel(float* __restrict__ attn)
{
    __shared__ float S[128 * 68];   // Q staging, then 2x K buffers (64*68 each)
    __shared__ float rs[256];

    const int qrow0 = blockIdx.x * 128;
    const int bh    = blockIdx.y;
    const float* qg = g_q + (size_t)bh * SEQ * DEPTH;
    const float* kg = g_k + (size_t)bh * SEQ * DEPTH;
    float* outp     = attn + (size_t)bh * SEQ * SEQ;

    const int tid  = threadIdx.x;
    const int lane = tid & 31, wid = tid >> 5;
    const int wm = wid >> 1, wn = wid & 1;
    const int rquad = lane >> 2, cquad = lane & 3;
    const int prow = tid >> 4, pc4 = tid & 15;

    // stage Q 128x64
    #pragma unroll
    for (int p = 0; p < 8; p++) {
        int row = prow + p * 16;
        *(float4*)(S + row * 68 + pc4 * 4) =
            *(const float4*)(qg + (size_t)(qrow0 + row) * DEPTH + pc4 * 4);
    }
    __syncthreads();

    // extract Q fragments, fold SCALE (exact: power of 2 keeps tf32 bits)
    uint32_t qa[2][8][4];
    #pragma unroll
    for (int mi = 0; mi < 2; mi++)
        #pragma unroll
        for (int ks = 0; ks < 8; ks++) {
            const float* qp = S + (wm * 32 + mi * 16 + rquad) * 68 + ks * 8 + cquad;
            qa[mi][ks][0] = __float_as_uint(qp[0] * SCALE);
            qa[mi][ks][1] = __float_as_uint(qp[8 * 68] * SCALE);
            qa[mi][ks][2] = __float_as_uint(qp[4] * SCALE);
            qa[mi][ks][3] = __float_as_uint(qp[8 * 68 + 4] * SCALE);
        }

    // prologue K tile 0
    float4 pk[4];
    #pragma unroll
    for (int p = 0; p < 4; p++)
        pk[p] = *(const float4*)(kg + (size_t)(prow + p * 16) * DEPTH + pc4 * 4);
    __syncthreads();   // everyone done extracting Q before S is overwritten
    #pragma unroll
    for (int p = 0; p < 4; p++)
        *(float4*)(S + (prow + p * 16) * 68 + pc4 * 4) = pk[p];

    float rowpart[4] = {0.f, 0.f, 0.f, 0.f};

    for (int it = 0; it < 32; it++) {
        __syncthreads();
        if (it + 1 < 32) {
            const int kcol0 = (it + 1) * 64;
            #pragma unroll
            for (int p = 0; p < 4; p++)
                pk[p] = *(const float4*)(kg + (size_t)(kcol0 + prow + p * 16) * DEPTH + pc4 * 4);
        }
        const float* Kb = S + (it & 1) * (64 * 68);
        const int kcol0 = it * 64;

        float c[2][4][4] = {};
        #pragma unroll
        for (int ks = 0; ks < 8; ks++) {
            uint32_t b[4][2];
            #pragma unroll
            for (int ni = 0; ni < 4; ni++) {
                const float* kp = Kb + (wn * 32 + ni * 8 + rquad) * 68 + ks * 8 + cquad;
                b[ni][0] = __float_as_uint(kp[0]);
                b[ni][1] = __float_as_uint(kp[4]);
            }
            #pragma unroll
            for (int mi = 0; mi < 2; mi++)
                #pragma unroll
                for (int ni = 0; ni < 4; ni++)
                    mma8(c[mi][ni], qa[mi][ks][0], qa[mi][ks][1], qa[mi][ks][2], qa[mi][ks][3],
                         b[ni][0], b[ni][1]);
        }

        #pragma unroll
        for (int mi = 0; mi < 2; mi++) {
            const int rA = qrow0 + wm * 32 + mi * 16 + rquad;
            #pragma unroll
            for (int ni = 0; ni < 4; ni++) {
                const int col = kcol0 + wn * 32 + ni * 8 + cquad * 2;
                float e0 = __expf(c[mi][ni][0]);
                float e1 = __expf(c[mi][ni][1]);
                float e2 = __expf(c[mi][ni][2]);
                float e3 = __expf(c[mi][ni][3]);
                rowpart[mi * 2 + 0] += e0 + e1;
                rowpart[mi * 2 + 1] += e2 + e3;
                *(float2*)(outp + (size_t)rA * SEQ + col)       = make_float2(e0, e1);
                *(float2*)(outp + (size_t)(rA + 8) * SEQ + col) = make_float2(e2, e3);
            }
        }

        if (it + 1 < 32) {
            float* Kn = S + ((it + 1) & 1) * (64 * 68);
            #pragma unroll
            for (int p = 0; p < 4; p++)
                *(float4*)(Kn + (prow + p * 16) * 68 + pc4 * 4) = pk[p];
        }
    }

    // deterministic rowsum reduction
    #pragma unroll
    for (int i = 0; i < 4; i++) {
        float v = rowpart[i];
        v += __shfl_xor_sync(0xffffffffu, v, 1);
        v += __shfl_xor_sync(0xffffffffu, v, 2);
        if (cquad == 0) {
            int rloc = wm * 32 + (i >> 1) * 16 + (i & 1) * 8 + rquad;
            rs[wn * 128 + rloc] = v;
        }
    }
    __syncthreads();
    if (tid < 128)
        g_rowsum[(size_t)bh * SEQ + qrow0 + tid] = rs[tid] + rs[128 + tid];
}

// ---------------------------------------------------------------------------
// K3: ctx = (raw attn @ v) * inv (row-linear); normalized attn written from
// prefetch registers. 64 q-rows/CTA; 8 warps = 2m x 4n, warp tile 32x16.
// Double-buffered attn + V tiles.
// ---------------------------------------------------------------------------
__global__ __launch_bounds__(256) void ctx_norm_kernel(float* __restrict__ attn)
{
    extern __shared__ float sm[];
    float* Ab   = sm;                    // [2][64*68] raw attn (tf32-rounded)
    float* Vb   = sm + 2 * 64 * 68;      // [2][64*68]
    float* invs = Vb + 2 * 64 * 68;      // [64]

    const int qrow0 = blockIdx.x * 64;
    const int bh    = blockIdx.y;
    const int b = bh >> 3, h = bh & 7;
    float* ap       = attn + (size_t)bh * SEQ * SEQ;
    const float* vg = g_v + (size_t)bh * SEQ * DEPTH;

    const int tid = threadIdx.x, lane = tid & 31, wid = tid >> 5;
    const int wm = wid >> 2, wn = wid & 3;
    const int rquad = lane >> 2, cquad = lane & 3;
    const int prow = tid >> 4, pc4 = tid & 15;

    if (tid < 64)
        invs[tid] = 1.0f / g_rowsum[(size_t)bh * SEQ + qrow0 + tid];
    __syncthreads();

    float4 pa[4], pv[4];
    // prologue tile 0
    #pragma unroll
    for (int p = 0; p < 4; p++) {
        int row = prow + p * 16;
        pa[p] = *(const float4*)(ap + (size_t)(qrow0 + row) * SEQ + pc4 * 4);
        pv[p] = *(const float4*)(vg + (size_t)row * DEPTH + pc4 * 4);
    }
    #pragma unroll
    for (int p = 0; p < 4; p++) {
        int row = prow + p * 16;
        float inv = invs[row];
        float4 w = pa[p];
        w.x *= inv; w.y *= inv; w.z *= inv; w.w *= inv;
        *(float4*)(ap + (size_t)(qrow0 + row) * SEQ + pc4 * 4) = w;   // final attn
        float4 rv;
        rv.x = __uint_as_float(f2tf32(pa[p].x));
        rv.y = __uint_as_float(f2tf32(pa[p].y));
        rv.z = __uint_as_float(f2tf32(pa[p].z));
        rv.w = __uint_as_float(f2tf32(pa[p].w));
        *(float4*)(Ab + row * 68 + pc4 * 4) = rv;
        *(float4*)(Vb + row * 68 + pc4 * 4) = pv[p];
    }

    float c[2][2][4] = {};

    for (int it = 0; it < 32; it++) {
        __syncthreads();
        if (it + 1 < 32) {
            const int s0 = (it + 1) * 64;
            #pragma unroll
            for (int p = 0; p < 4; p++) {
                int row = prow + p * 16;
                pa[p] = *(const float4*)(ap + (size_t)(qrow0 + row) * SEQ + s0 + pc4 * 4);
                pv[p] = *(const float4*)(vg + (size_t)(s0 + row) * DEPTH + pc4 * 4);
            }
        }
        const float* As = Ab + (it & 1) * (64 * 68);
        const float* Vs = Vb + (it & 1) * (64 * 68);

        #pragma unroll
        for (int ks = 0; ks < 8; ks++) {
            uint32_t a[2][4];
            #pragma unroll
            for (int mi = 0; mi < 2; mi++) {
                const float* apm = As + (wm * 32 + mi * 16 + rquad) * 68 + ks * 8 + cquad;
                a[mi][0] = __float_as_uint(apm[0]);
                a[mi][1] = __float_as_uint(apm[8 * 68]);
                a[mi][2] = __float_as_uint(apm[4]);
                a[mi][3] = __float_as_uint(apm[8 * 68 + 4]);
            }
            uint32_t bb[2][2];
            #pragma unroll
            for (int ni = 0; ni < 2; ni++) {
                const float* vp = Vs + (ks * 8 + cquad) * 68 + wn * 16 + ni * 8 + rquad;
                bb[ni][0] = __float_as_uint(vp[0]);
                bb[ni][1] = __float_as_uint(vp[4 * 68]);
            }
            #pragma unroll
            for (int mi = 0; mi < 2; mi++)
                #pragma unroll
                for (int ni = 0; ni < 2; ni++)
                    mma8(c[mi][ni], a[mi][0], a[mi][1], a[mi][2], a[mi][3],
                         bb[ni][0], bb[ni][1]);
        }

        if (it + 1 < 32) {
            const int s0 = (it + 1) * 64;
            float* An = Ab + ((it + 1) & 1) * (64 * 68);
            float* Vn = Vb + ((it + 1) & 1) * (64 * 68);
            #pragma unroll
            for (int p = 0; p < 4; p++) {
                int row = prow + p * 16;
                float inv = invs[row];
                float4 w = pa[p];
                w.x *= inv; w.y *= inv; w.z *= inv; w.w *= inv;
                *(float4*)(ap + (size_t)(qrow0 + row) * SEQ + s0 + pc4 * 4) = w;
                float4 rv;
                rv.x = __uint_as_float(f2tf32(pa[p].x));
                rv.y = __uint_as_float(f2tf32(pa[p].y));
                rv.z = __uint_as_float(f2tf32(pa[p].z));
                rv.w = __uint_as_float(f2tf32(pa[p].w));
                *(float4*)(An + row * 68 + pc4 * 4) = rv;
                *(float4*)(Vn + row * 68 + pc4 * 4) = pv[p];
            }
        }
    }

    // epilogue: scale ctx rows by inv, write
    #pragma unroll
    for (int mi = 0; mi < 2; mi++) {
        const int rloc = wm * 32 + mi * 16 + rquad;
        const float i0 = invs[rloc], i1 = invs[rloc + 8];
        const int r = qrow0 + rloc;
        #pragma unroll
        for (int ni = 0; ni < 2; ni++) {
            const int col = h * 64 + wn * 16 + ni * 8 + cquad * 2;
            *(float2*)(g_ctx + (size_t)(b * SEQ + r) * DMODEL + col) =
                make_float2(c[mi][ni][0] * i0, c[mi][ni][1] * i0);
            *(float2*)(g_ctx + (size_t)(b * SEQ + r + 8) * DMODEL + col) =
                make_float2(c[mi][ni][2] * i1, c[mi][ni][3] * i1);
        }
    }
}

// ---------------------------------------------------------------------------
extern "C" void kernel_launch(void* const* d_in, const int* in_sizes, int n_in,
                              void* d_out, int out_size)
{
    const float* x  = (const float*)d_in[0];
    const float* Wq = (const float*)d_in[1];
    const float* bq = (const float*)d_in[2];
    const float* Wk = (const float*)d_in[3];
    const float* bk = (const float*)d_in[4];
    const float* Wv = (const float*)d_in[5];
    const float* bv = (const float*)d_in[6];
    const float* Wo = (const float*)d_in[7];
    const float* bo = (const float*)d_in[8];

    float* out  = (float*)d_out;
    float* attn = out + (size_t)ROWS * DMODEL;

    const int smem_gemm = (2 * 128 * 36 + 2 * 32 * 68) * 4;      // 54272
    const int smem_k3   = (2 * 64 * 68 + 2 * 64 * 68 + 64) * 4;  // 69888
    cudaFuncSetAttribute(gemm_tf32<0>, cudaFuncAttributeMaxDynamicSharedMemorySize, smem_gemm);
    cudaFuncSetAttribute(gemm_tf32<1>, cudaFuncAttributeMaxDynamicSharedMemorySize, smem_gemm);
    cudaFuncSetAttribute(ctx_norm_kernel, cudaFuncAttributeMaxDynamicSharedMemorySize, smem_k3);

    gemm_tf32<0><<<dim3(DMODEL / 64, ROWS / 128, 3), 256, smem_gemm>>>(
        x, Wq, bq, Wk, bk, Wv, bv, nullptr);
    logits_exp_kernel<<<dim3(SEQ / 128, BH), 256>>>(attn);
    ctx_norm_kernel<<<dim3(SEQ / 64, BH), 256, smem_k3>>>(attn);
    gemm_tf32<1><<<dim3(DMODEL / 64, ROWS / 128, 1), 256, smem_gemm>>>(
        nullptr, Wo, bo, nullptr, nullptr, nullptr, nullptr, out);
}